// round 3
// baseline (speedup 1.0000x reference)
#include <cuda_runtime.h>

typedef unsigned long long ULL;

#define NBLK   128
#define NTHR   256
#define ROWS   32      // batch rows per block
#define H      64
#define T128   128
#define STEPS  60
#define HPAD   36      // padded row length for hT (floats)

__device__ __forceinline__ ULL fma2(ULL a, ULL b, ULL c) {
    ULL d;
    asm("fma.rn.f32x2 %0, %1, %2, %3;" : "=l"(d) : "l"(a), "l"(b), "l"(c));
    return d;
}
__device__ __forceinline__ ULL pack2(float x, float y) {
    ULL r;
    asm("mov.b64 %0, {%1, %2};" : "=l"(r) : "f"(x), "f"(y));
    return r;
}
__device__ __forceinline__ void unpack2(ULL v, float& x, float& y) {
    asm("mov.b64 {%0, %1}, %2;" : "=f"(x), "=f"(y) : "l"(v));
}
__device__ __forceinline__ float ex2f_(float x) {
    float y; asm("ex2.approx.f32 %0, %1;" : "=f"(y) : "f"(x)); return y;
}
__device__ __forceinline__ float rcpf_(float x) {
    float y; asm("rcp.approx.f32 %0, %1;" : "=f"(y) : "f"(x)); return y;
}
// sigmoid(x) = 1/(1+2^(-x*log2e)); tanh(x) = 2*sigmoid(2x)-1. (MUFU-based, ~1e-6 rel err)
__device__ __forceinline__ float sigm(float x) {
    return rcpf_(1.0f + ex2f_(-1.4426950408889634f * x));
}
__device__ __forceinline__ float tanh_(float x) {
    return fmaf(2.0f, rcpf_(1.0f + ex2f_(-2.8853900817779268f * x)), -1.0f);
}

// One 64-k matvec chunk: acc[gb][pair] += W[k][j][gb] * h[k][R0 + 2*pair + {0,1}]
__device__ __forceinline__ void mv64(const float* __restrict__ Wb,
                                     const float* __restrict__ hb,
                                     int j, int R0, ULL acc[4][4]) {
#pragma unroll 4
    for (int k = 0; k < 64; k++) {
        float4 w = *(const float4*)(Wb + (k * 64 + j) * 4);
        const float* hr = hb + k * HPAD + R0;
        ulonglong2 hA = *(const ulonglong2*)(hr);       // rows R0..R0+3
        ulonglong2 hB = *(const ulonglong2*)(hr + 4);   // rows R0+4..R0+7
        ULL wp;
        wp = pack2(w.x, w.x);
        acc[0][0] = fma2(wp, hA.x, acc[0][0]); acc[0][1] = fma2(wp, hA.y, acc[0][1]);
        acc[0][2] = fma2(wp, hB.x, acc[0][2]); acc[0][3] = fma2(wp, hB.y, acc[0][3]);
        wp = pack2(w.y, w.y);
        acc[1][0] = fma2(wp, hA.x, acc[1][0]); acc[1][1] = fma2(wp, hA.y, acc[1][1]);
        acc[1][2] = fma2(wp, hB.x, acc[1][2]); acc[1][3] = fma2(wp, hB.y, acc[1][3]);
        wp = pack2(w.z, w.z);
        acc[2][0] = fma2(wp, hA.x, acc[2][0]); acc[2][1] = fma2(wp, hA.y, acc[2][1]);
        acc[2][2] = fma2(wp, hB.x, acc[2][2]); acc[2][3] = fma2(wp, hB.y, acc[2][3]);
        wp = pack2(w.w, w.w);
        acc[3][0] = fma2(wp, hA.x, acc[3][0]); acc[3][1] = fma2(wp, hA.y, acc[3][1]);
        acc[3][2] = fma2(wp, hB.x, acc[3][2]); acc[3][3] = fma2(wp, hB.y, acc[3][3]);
    }
}

// LSTM cell pointwise: gates (i,f,g,o) in acc -> new c (in-place) and new h
__device__ __forceinline__ void cell(ULL a[4][4], float c[8], float hn[8]) {
#pragma unroll
    for (int p = 0; p < 4; p++) {
        float i0, i1, f0, f1, g0, g1, o0, o1;
        unpack2(a[0][p], i0, i1);
        unpack2(a[1][p], f0, f1);
        unpack2(a[2][p], g0, g1);
        unpack2(a[3][p], o0, o1);
        float cn0 = sigm(f0) * c[2 * p]     + sigm(i0) * tanh_(g0);
        float cn1 = sigm(f1) * c[2 * p + 1] + sigm(i1) * tanh_(g1);
        c[2 * p]     = cn0;
        c[2 * p + 1] = cn1;
        hn[2 * p]     = sigm(o0) * tanh_(cn0);
        hn[2 * p + 1] = sigm(o1) * tanh_(cn1);
    }
}

// SMEM layout (floats):
//  W0   [64][64][4]   : Whh0 repacked, W0[(k*64+j)*4+gb] = Whh0[gb*64+j][k]
//  W1   [128][64][4]  : k<64 -> Wih1 (input = h0_new), k>=64 -> Whh1 (input = h1_old)
//  h0T  [64][HPAD]    : transposed h0 state, h0T[k*HPAD + r]
//  h1T  [64][HPAD]
//  xs   [32][4]       : current step input per row
//  Wfs  [64][4]       : Wfc transposed
//  bfs  [4]
#define OFF_W0   0
#define OFF_W1   (OFF_W0 + 64 * 64 * 4)
#define OFF_H0   (OFF_W1 + 128 * 64 * 4)
#define OFF_H1   (OFF_H0 + 64 * HPAD)
#define OFF_XS   (OFF_H1 + 64 * HPAD)
#define OFF_WFS  (OFF_XS + ROWS * 4)
#define OFF_BFS  (OFF_WFS + 64 * 4)
#define SMEM_FLOATS (OFF_BFS + 4)

__global__ __launch_bounds__(NTHR, 1)
void lstm_persist_kernel(const float* __restrict__ x,
                         const float* __restrict__ Wih0, const float* __restrict__ Whh0,
                         const float* __restrict__ bih0, const float* __restrict__ bhh0,
                         const float* __restrict__ Wih1, const float* __restrict__ Whh1,
                         const float* __restrict__ bih1, const float* __restrict__ bhh1,
                         const float* __restrict__ Wfc,  const float* __restrict__ bfc,
                         float* __restrict__ out) {
    extern __shared__ float sm[];
    float* W0  = sm + OFF_W0;
    float* W1  = sm + OFF_W1;
    float* h0T = sm + OFF_H0;
    float* h1T = sm + OFF_H1;
    float* xs  = sm + OFF_XS;
    float* Wfs = sm + OFF_WFS;
    float* bfs = sm + OFF_BFS;

    const int t = threadIdx.x;
    const int bid = blockIdx.x;

    // ---- one-time staging: repack weights into gate-interleaved k-major layout ----
    for (int idx = t; idx < 64 * 64 * 4; idx += NTHR) {
        int gb = idx & 3, jj = (idx >> 2) & 63, k = idx >> 8;
        W0[idx] = Whh0[(gb * 64 + jj) * 64 + k];
    }
    for (int idx = t; idx < 128 * 64 * 4; idx += NTHR) {
        int gb = idx & 3, jj = (idx >> 2) & 63, k = idx >> 8;
        W1[idx] = (k < 64) ? Wih1[(gb * 64 + jj) * 64 + k]
                           : Whh1[(gb * 64 + jj) * 64 + (k - 64)];
    }
    for (int idx = t; idx < 64 * HPAD; idx += NTHR) { h0T[idx] = 0.0f; h1T[idx] = 0.0f; }
    for (int idx = t; idx < 64 * 4; idx += NTHR) {
        int d = idx & 3, k = idx >> 2;
        Wfs[idx] = Wfc[d * 64 + k];
    }
    if (t < 4) bfs[t] = bfc[t];

    // per-thread assignment: hidden unit j (4 gates), row group rg (8 rows)
    const int j  = t & 63;
    const int rg = t >> 6;
    const int R0 = rg * 8;

    float b0r[4], b1r[4], wi0[4][4];
#pragma unroll
    for (int gb = 0; gb < 4; gb++) {
        b0r[gb] = bih0[gb * 64 + j] + bhh0[gb * 64 + j];
        b1r[gb] = bih1[gb * 64 + j] + bhh1[gb * 64 + j];
#pragma unroll
        for (int d = 0; d < 4; d++) wi0[gb][d] = Wih0[(gb * 64 + j) * 4 + d];
    }
    float c0[8], c1[8];
#pragma unroll
    for (int r = 0; r < 8; r++) { c0[r] = 0.0f; c1[r] = 0.0f; }

    const int rowbase = bid * ROWS;
    __syncthreads();

    for (int s = 0; s < T128 + STEPS; s++) {
        // stage this step's input (encode phase reads x; AR phase reuses xs = pred
        // written by the head; s==128 reuses xs = x[:,127] left over from s==127)
        if (s < T128 && t < ROWS * 4) {
            int r = t >> 2, d = t & 3;
            xs[t] = x[((size_t)(rowbase + r) * T128 + s) * 4 + d];
        }
        __syncthreads();

        // -------- layer 0: gates = b0 + Wih0*x + Whh0*h0 --------
        ULL a0[4][4];
#pragma unroll
        for (int gb = 0; gb < 4; gb++) {
#pragma unroll
            for (int p = 0; p < 4; p++) {
                int r = 2 * p;
                float e0 = b0r[gb], e1 = b0r[gb];
#pragma unroll
                for (int d = 0; d < 4; d++) {
                    e0 = fmaf(wi0[gb][d], xs[(R0 + r) * 4 + d], e0);
                    e1 = fmaf(wi0[gb][d], xs[(R0 + r + 1) * 4 + d], e1);
                }
                a0[gb][p] = pack2(e0, e1);
            }
        }
        mv64(W0, h0T, j, R0, a0);

        // -------- layer 1 partial (Whh1 * h1_old) — overlaps layer-0 MUFU --------
        ULL a1[4][4];
#pragma unroll
        for (int gb = 0; gb < 4; gb++)
#pragma unroll
            for (int p = 0; p < 4; p++) a1[gb][p] = pack2(b1r[gb], b1r[gb]);
        mv64(W1 + 64 * 64 * 4, h1T, j, R0, a1);

        float h0n[8];
        cell(a0, c0, h0n);

        __syncthreads();   // everyone done reading old h0T / old h1T
        *(float4*)(h0T + j * HPAD + R0)     = make_float4(h0n[0], h0n[1], h0n[2], h0n[3]);
        *(float4*)(h0T + j * HPAD + R0 + 4) = make_float4(h0n[4], h0n[5], h0n[6], h0n[7]);
        __syncthreads();   // new h0T visible

        // -------- layer 1 remaining (Wih1 * h0_new) --------
        mv64(W1, h0T, j, R0, a1);
        float h1n[8];
        cell(a1, c1, h1n);

        __syncthreads();   // everyone done reading old h1T
        *(float4*)(h1T + j * HPAD + R0)     = make_float4(h1n[0], h1n[1], h1n[2], h1n[3]);
        *(float4*)(h1T + j * HPAD + R0 + 4) = make_float4(h1n[4], h1n[5], h1n[6], h1n[7]);
        __syncthreads();   // new h1T visible

        // -------- output head (AR phase): pred = Wfc * h1 + bfc --------
        if (s >= T128 && t < ROWS * 4) {
            int r = t >> 2, d = t & 3;
            float p = bfs[d];
#pragma unroll 8
            for (int k = 0; k < 64; k++)
                p = fmaf(Wfs[k * 4 + d], h1T[k * HPAD + r], p);
            xs[t] = p;  // next step's input (read after next top-of-loop barrier)
            out[((size_t)(rowbase + r) * STEPS + (s - T128)) * 4 + d] = p;
        }
        // top-of-loop __syncthreads() orders xs/pred for the next step
    }
}

extern "C" void kernel_launch(void* const* d_in, const int* in_sizes, int n_in,
                              void* d_out, int out_size) {
    const float* x    = (const float*)d_in[0];
    const float* Wih0 = (const float*)d_in[1];
    const float* Whh0 = (const float*)d_in[2];
    const float* bih0 = (const float*)d_in[3];
    const float* bhh0 = (const float*)d_in[4];
    const float* Wih1 = (const float*)d_in[5];
    const float* Whh1 = (const float*)d_in[6];
    const float* bih1 = (const float*)d_in[7];
    const float* bhh1 = (const float*)d_in[8];
    const float* Wfc  = (const float*)d_in[9];
    const float* bfc  = (const float*)d_in[10];

    const int smem_bytes = SMEM_FLOATS * (int)sizeof(float);  // ~216.6 KB
    cudaFuncSetAttribute(lstm_persist_kernel,
                         cudaFuncAttributeMaxDynamicSharedMemorySize, smem_bytes);
    lstm_persist_kernel<<<NBLK, NTHR, smem_bytes>>>(
        x, Wih0, Whh0, bih0, bhh0, Wih1, Whh1, bih1, bhh1, Wfc, bfc, (float*)d_out);
}